// round 17
// baseline (speedup 1.0000x reference)
#include <cuda_runtime.h>
#include <cuda_fp16.h>
#include <cstdint>

#define LEN_M   131328
#define D_H     256
#define N_MC    64
#define DDP1    513
#define NROWS   4096
#define NCOL    512        // interleaved: col 2h = A_h (m), 2h+1 = B_h (s)
#define KP      512        // MMA K (col 512 handled as rank-1 update)
#define NCHUNK  8          // 512 / 64
#define BKB     128        // bytes per smem row (64 fp16) = SW128 atom

// -------- persistent scratch (no allocs allowed) ---------------------------
__device__ __align__(128) __half g_x16[NROWS * KP];        // x in fp16
__device__ __align__(128) __half g_b16[NCOL * KP];         // row 2h=m_h, 2h+1=s_h
__device__ __align__(128) float g_x512[NROWS];
__device__ __align__(128) float g_w512[NCOL];              // interleaved m/s

// -------- PTX helpers -------------------------------------------------------
__device__ __forceinline__ uint32_t s2u(const void* p) {
    uint32_t a;
    asm("{ .reg .u64 t; cvta.to.shared.u64 t, %1; cvt.u32.u64 %0, t; }"
        : "=r"(a) : "l"(p));
    return a;
}
#define SW128(o) ((o) ^ (((o) >> 3) & 0x70))

#define LDSM_X4(r, a)                                                         \
    asm volatile("ldmatrix.sync.aligned.m8n8.x4.shared.b16 {%0,%1,%2,%3}, [%4];" \
        : "=r"((r)[0]), "=r"((r)[1]), "=r"((r)[2]), "=r"((r)[3]) : "r"(a))

#define MMA16816F16(d, a, b)                                                  \
    asm volatile("mma.sync.aligned.m16n8k16.row.col.f32.f16.f16.f32 "         \
        "{%0,%1,%2,%3}, {%4,%5,%6,%7}, {%8,%9}, {%0,%1,%2,%3};"               \
        : "+f"((d)[0]), "+f"((d)[1]), "+f"((d)[2]), "+f"((d)[3])              \
        : "r"((a)[0]), "r"((a)[1]), "r"((a)[2]), "r"((a)[3]),                 \
          "r"((b)[0]), "r"((b)[1]))

__device__ __forceinline__ uint16_t hfbits(float f) {
    __half h = __float2half_rn(f);
    return *(uint16_t*)&h;
}

typedef unsigned long long ull;
union F2U { float2 f; ull u; };
__device__ __forceinline__ ull fma2(ull a, ull b, ull c) {
    ull r; asm("fma.rn.f32x2 %0, %1, %2, %3;" : "=l"(r) : "l"(a), "l"(b), "l"(c));
    return r;
}
__device__ __forceinline__ ull pk2(float x, float y) {
    ull r; asm("mov.b64 %0, {%1,%2};" : "=l"(r) : "f"(x), "f"(y)); return r;
}

// DSMEM read: float4 from the same smem offset in cluster CTA `rank`
__device__ __forceinline__ float4 dsmem_ld4(uint32_t saddr, uint32_t rank) {
    uint32_t ra;
    asm volatile("mapa.shared::cluster.u32 %0, %1, %2;"
                 : "=r"(ra) : "r"(saddr), "r"(rank));
    float4 v;
    asm volatile("ld.shared::cluster.v4.f32 {%0,%1,%2,%3}, [%4];"
                 : "=f"(v.x), "=f"(v.y), "=f"(v.z), "=f"(v.w) : "r"(ra));
    return v;
}
#define CLUSTER_ARRIVE() asm volatile("barrier.cluster.arrive.aligned;" ::: "memory")
#define CLUSTER_WAIT()   asm volatile("barrier.cluster.wait.aligned;" ::: "memory")

// -------- Kernel 1: fused prep (ONE launch) ---------------------------------
// blocks 0..127 : weights d = 4b..4b+3 (smem transpose, 5KB smem)
// block  128    : weight row d = 512
// blocks 129..  : x rows (4 per block, 8 floats/thread, one uint4 store)
#define DCHUNK 4
#define XBLK0  129

__global__ __launch_bounds__(256) void prep_all(
        const float* __restrict__ params, const float* __restrict__ x,
        float* __restrict__ out_m, float* __restrict__ out_v) {
    const int b   = blockIdx.x;
    const int tid = threadIdx.x;

    if (b < 128) {
        __shared__ uint16_t tmh[256][DCHUNK + 1];
        __shared__ uint16_t tsh[256][DCHUNK + 1];
        const int h = tid;
        #pragma unroll
        for (int j = 0; j < DCHUNK; j++) {
            int d = b * DCHUNK + j;
            int i = d * 256 + h;
            float m = params[i];                       // coalesced
            float v = fmaxf(params[LEN_M + i], 0.0f) + 1e-6f;
            float s = sqrtf(v);
            out_m[i] = m;
            out_v[i] = v;
            tmh[h][j] = hfbits(m);
            tsh[h][j] = hfbits(s);
        }
        __syncthreads();
        const int colB = b * DCHUNK;
        auto pack = [&](uint16_t (*t)[DCHUNK + 1], int hh) -> uint2 {
            uint2 w;
            w.x = (uint32_t)t[hh][0] | ((uint32_t)t[hh][1] << 16);
            w.y = (uint32_t)t[hh][2] | ((uint32_t)t[hh][3] << 16);
            return w;
        };
        #pragma unroll
        for (int rr = 0; rr < 2; rr++) {               // rows tid, tid+256
            int r  = tid + rr * 256;
            int hh = r >> 1;
            uint2 w = (r & 1) ? pack(tsh, hh) : pack(tmh, hh);
            *(uint2*)(g_b16 + (size_t)r * KP + colB) = w;
        }
    } else if (b == 128) {
        const int h = tid;                              // d = 512 row
        int i = 512 * 256 + h;
        float m = params[i];
        float v = fmaxf(params[LEN_M + i], 0.0f) + 1e-6f;
        out_m[i] = m;
        out_v[i] = v;
        g_w512[2 * h]     = m;
        g_w512[2 * h + 1] = sqrtf(v);
    } else {
        // x: 4 rows per block, 64 threads/row, 8 floats/thread -> one uint4
        const int r = tid >> 6;             // 0..3
        const int t = tid & 63;
        const int n = (b - XBLK0) * 4 + r;
        const size_t base = (size_t)n * DDP1 + 8 * t;
        float v[8];
        #pragma unroll
        for (int i = 0; i < 8; i++) v[i] = x[base + i];
        uint32_t hw[4];
        #pragma unroll
        for (int i = 0; i < 4; i++)
            hw[i] = (uint32_t)hfbits(v[2 * i]) | ((uint32_t)hfbits(v[2 * i + 1]) << 16);
        ((uint4*)g_x16)[n * 64 + t] = make_uint4(hw[0], hw[1], hw[2], hw[3]);
        if (t == 0) g_x512[n] = x[(size_t)n * DDP1 + 512];
    }
}

// -------- Kernel 2: fp16 HMMA GEMM + FUSED MC epilogue + DSMEM reduce -------
// grid (4, 64), cluster (4,1,1). Tile 64(M) x 128(N interleaved = 64 h).
// 8 warps 2(M)x4(N), warp tile 32x32. 2 CTAs/SM so one CTA's epilogue (fma)
// overlaps the co-resident CTA's mainloop (tensor/loads).
#define MTILE    64
#define TILE_XB  8192                   // 64 rows x 128B (x tile)
#define TILE_BB  16384                  // 128 rows x 128B (b tile)
#define CHSET_B  (TILE_XB + TILE_BB)    // 24KB per stage
#define NSTAGE   3
#define ABSTRIDE 132
#define PB_OFF   (1024 + NSTAGE * CHSET_B)        // 74752
#define GSMEM    (PB_OFF + MTILE * N_MC * 4)      // 91136 -> 2 CTAs/SM
#define NTHREADS 256

__global__ __launch_bounds__(NTHREADS, 2) __cluster_dims__(4, 1, 1)
void gemm_fused(const float* __restrict__ W1,
                const float* __restrict__ eps,
                float* __restrict__ out_pred) {
    extern __shared__ __align__(1024) char smem[];
    const uint32_t sb = s2u(smem);
    float* sw512 = (float*)smem;              // [0,512): 128 floats (interleaved)
    float* sW1   = (float*)(smem + 512);      // 64 floats W1[hBase+1 ..]
    float* sEps  = (float*)(smem + 768);      // 64 floats
    const uint32_t TB = sb + 1024;

    const int tid  = threadIdx.x;
    const int lane = tid & 31;
    const int warp = tid >> 5;
    const int wm = warp >> 2;                 // 0..1 (32 rows each)
    const int wn = warp & 3;                  // 0..3 (32 interleaved cols = 16 h)
    const int rowBase = blockIdx.y * MTILE;
    const int colBase = blockIdx.x * 128;
    const int hBase   = blockIdx.x * 64;

    if (tid < 128)                  sw512[tid]       = g_w512[colBase + tid];
    else if (tid < 192)             sW1[tid - 128]   = W1[hBase + (tid - 128) + 1];
    else                            sEps[tid - 192]  = eps[tid - 192];

    // hoisted epilogue operands
    float xv[4];
    #pragma unroll
    for (int mi = 0; mi < 2; mi++) {
        int r = rowBase + wm * 32 + mi * 16 + (lane >> 2);
        xv[2 * mi]     = g_x512[r];
        xv[2 * mi + 1] = g_x512[r + 8];
    }

    float acc[2][4][4];
    #pragma unroll
    for (int mi = 0; mi < 2; mi++)
        #pragma unroll
        for (int nj = 0; nj < 4; nj++)
            #pragma unroll
            for (int q = 0; q < 4; q++)
                acc[mi][nj][q] = 0.0f;

    auto issue_chunk = [&](int c, int buf) {
        const uint32_t tb = TB + buf * CHSET_B;
        // x tile: 64 rows x 8 slots = 512 slots
        #pragma unroll
        for (int i = 0; i < 2; i++) {
            int q = tid + i * NTHREADS;
            int r = q >> 3, s = q & 7;
            const char* gp = (const char*)g_x16 + (size_t)(rowBase + r) * (KP * 2)
                           + c * BKB + s * 16;
            uint32_t sp = tb + SW128(r * BKB + s * 16);
            asm volatile("cp.async.cg.shared.global [%0], [%1], 16;"
                         :: "r"(sp), "l"(gp));
        }
        // b tile: 128 rows x 8 slots = 1024 slots
        #pragma unroll
        for (int i = 0; i < 4; i++) {
            int q = tid + i * NTHREADS;
            int r = q >> 3, s = q & 7;
            const char* gp = (const char*)g_b16 + (size_t)(colBase + r) * (KP * 2)
                           + c * BKB + s * 16;
            uint32_t sp = tb + TILE_XB + SW128(r * BKB + s * 16);
            asm volatile("cp.async.cg.shared.global [%0], [%1], 16;"
                         :: "r"(sp), "l"(gp));
        }
        asm volatile("cp.async.commit_group;" ::: "memory");
    };

    issue_chunk(0, 0);
    issue_chunk(1, 1);

    #pragma unroll
    for (int c = 0; c < NCHUNK; c++) {
        const int buf = c % NSTAGE;           // constant after unroll

        if (c < NCHUNK - 1) {
            asm volatile("cp.async.wait_group 1;" ::: "memory");
        } else {
            asm volatile("cp.async.wait_group 0;" ::: "memory");
        }
        __syncthreads();
        if (c + 2 < NCHUNK)
            issue_chunk(c + 2, (c + 2) % NSTAGE);

        const uint32_t Ah = TB + buf * CHSET_B;
        const uint32_t Bh = Ah + TILE_XB;

        #pragma unroll
        for (int s = 0; s < 4; s++) {
            const int k0 = s * 16;
            uint32_t ah[2][4], bhf[4][2];

            #pragma unroll
            for (int mi = 0; mi < 2; mi++) {
                int row = wm * 32 + mi * 16 + (lane & 15);
                int col = k0 + ((lane >> 4) << 3);
                uint32_t off = SW128(row * BKB + col * 2);
                LDSM_X4(ah[mi], Ah + off);
            }
            #pragma unroll
            for (int p = 0; p < 2; p++) {
                int row = wn * 32 + p * 16 + (lane & 7) + ((lane & 16) >> 1);
                int col = k0 + (lane & 8);
                uint32_t off = SW128(row * BKB + col * 2);
                uint32_t r[4];
                LDSM_X4(r, Bh + off);
                bhf[p * 2][0] = r[0]; bhf[p * 2][1] = r[1];
                bhf[p * 2 + 1][0] = r[2]; bhf[p * 2 + 1][1] = r[3];
            }

            #pragma unroll
            for (int mi = 0; mi < 2; mi++)
                #pragma unroll
                for (int nj = 0; nj < 4; nj++)
                    MMA16816F16(acc[mi][nj], ah[mi], bhf[nj]);
        }
    }

    // ---- stage (a,b) pairs into smem (reuse pipeline region) ----
    __syncthreads();                     // all MMA smem reads done

    float* AB = (float*)(smem + 1024);   // [row][ABSTRIDE]: (a,b) x 64 h
    #pragma unroll
    for (int mi = 0; mi < 2; mi++) {
        int r0 = wm * 32 + mi * 16 + (lane >> 2);
        #pragma unroll
        for (int nj = 0; nj < 4; nj++) {
            int h = wn * 16 + nj * 4 + (lane & 3);
            float wmv = sw512[2 * h], wsv = sw512[2 * h + 1];
            float2 v0 = { acc[mi][nj][0] + xv[2 * mi] * wmv,
                          acc[mi][nj][1] + xv[2 * mi] * wsv };
            float2 v1 = { acc[mi][nj][2] + xv[2 * mi + 1] * wmv,
                          acc[mi][nj][3] + xv[2 * mi + 1] * wsv };
            *(float2*)&AB[r0 * ABSTRIDE + 2 * h]       = v0;
            *(float2*)&AB[(r0 + 8) * ABSTRIDE + 2 * h] = v1;
        }
    }
    __syncthreads();

    // ---- fused MC epilogue: thread = (row, mc-quarter of 16) ----
    const int row = tid >> 2;            // 0..63
    const int g   = tid & 3;

    ull e2[8];
    #pragma unroll
    for (int j = 0; j < 8; j++)
        e2[j] = ((const ull*)(sEps + g * 16))[j];

    ull acc2[8];
    #pragma unroll
    for (int j = 0; j < 8; j++) acc2[j] = 0ull;

    const float* abrow = &AB[row * ABSTRIDE];

    #pragma unroll 4
    for (int h2 = 0; h2 < 32; h2++) {            // two h per iteration
        float4 ab = *(const float4*)&abrow[4 * h2];      // a0,b0,a1,b1
        float2 ww = *(const float2*)&sW1[2 * h2];
        ull a0d = pk2(ab.x, ab.x), b0d = pk2(ab.y, ab.y);
        ull a1d = pk2(ab.z, ab.z), b1d = pk2(ab.w, ab.w);
        ull w0d = pk2(ww.x, ww.x), w1d = pk2(ww.y, ww.y);
        #pragma unroll
        for (int j = 0; j < 8; j++) {
            F2U t; t.u = fma2(e2[j], b0d, a0d);
            t.f.x = fmaxf(t.f.x, 0.0f); t.f.y = fmaxf(t.f.y, 0.0f);
            acc2[j] = fma2(t.u, w0d, acc2[j]);
            F2U s; s.u = fma2(e2[j], b1d, a1d);
            s.f.x = fmaxf(s.f.x, 0.0f); s.f.y = fmaxf(s.f.y, 0.0f);
            acc2[j] = fma2(s.u, w1d, acc2[j]);
        }
    }

    // partial -> SMEM (this CTA's h-quarter contribution, 64 rows x 64 mc)
    float* P = (float*)(smem + PB_OFF) + row * N_MC + g * 16;
    #pragma unroll
    for (int q = 0; q < 4; q++) {
        F2U lo, hi; lo.u = acc2[2 * q]; hi.u = acc2[2 * q + 1];
        float4 o = { lo.f.x, lo.f.y, hi.f.x, hi.f.y };
        *(float4*)(P + 4 * q) = o;
    }

    // ---- cluster DSMEM reduce: rank r outputs rows [16r, 16r+16) ----------
    CLUSTER_ARRIVE();                    // release: my P writes visible
    CLUSTER_WAIT();                      // acquire: all peers' P visible

    const uint32_t rank = blockIdx.x;    // cluster spans x: rank == bx
    const uint32_t sP   = sb + PB_OFF;
    const float w0 = W1[0];
    float4* OP = (float4*)out_pred;
    {
        int p4 = rank * 256 + tid;                 // float4 idx in P (1024 total)
        uint32_t addr = sP + p4 * 16;
        float4 a = dsmem_ld4(addr, 0);
        float4 b = dsmem_ld4(addr, 1);
        float4 c = dsmem_ld4(addr, 2);
        float4 d = dsmem_ld4(addr, 3);
        float4 o;                                  // fixed order: deterministic
        o.x = w0 + ((a.x + b.x) + (c.x + d.x));
        o.y = w0 + ((a.y + b.y) + (c.y + d.y));
        o.z = w0 + ((a.z + b.z) + (c.z + d.z));
        o.w = w0 + ((a.w + b.w) + (c.w + d.w));
        OP[rowBase * 16 + p4] = o;                 // 16 float4 per row
    }

    CLUSTER_ARRIVE();                    // keep peer smem alive until all read
    CLUSTER_WAIT();
}

// ---------------------------------------------------------------------------
extern "C" void kernel_launch(void* const* d_in, const int* in_sizes, int n_in,
                              void* d_out, int out_size) {
    const float* params = (const float*)d_in[0];
    const float* W1     = (const float*)d_in[1];
    const float* x      = (const float*)d_in[2];
    const float* eps    = (const float*)d_in[3];

    float* out      = (float*)d_out;
    float* out_pred = out;
    float* out_m    = out + NROWS * N_MC;
    float* out_v    = out_m + LEN_M;

    cudaFuncSetAttribute(gemm_fused, cudaFuncAttributeMaxDynamicSharedMemorySize, GSMEM);

    prep_all<<<XBLK0 + NROWS / 4, 256>>>(params, x, out_m, out_v);
    gemm_fused<<<dim3(4, NROWS / MTILE), NTHREADS, GSMEM>>>(W1, eps, out_pred);
}